// round 11
// baseline (speedup 1.0000x reference)
#include <cuda_runtime.h>

#define B_TOTAL 2048
#define NPTS    256

typedef unsigned long long ull;

__device__ float g_partial[B_TOTAL];
__device__ int   g_ctr;    // zero-init; last block resets it each run

__device__ __forceinline__ ull pk2(float lo, float hi) {
    ull r; asm("mov.b64 %0, {%1, %2};" : "=l"(r) : "f"(lo), "f"(hi)); return r;
}
// Packed 2-wide fp32 FMA (sm_103a FFMA2; only reachable via PTX f32x2).
__device__ __forceinline__ ull ffma2(ull a, ull b, ull c) {
    ull d; asm("fma.rn.f32x2 %0, %1, %2, %3;" : "=l"(d) : "l"(a), "l"(b), "l"(c));
    return d;
}
__device__ __forceinline__ unsigned lo32(ull v) { return (unsigned)v; }
__device__ __forceinline__ unsigned hi32(ull v) { return (unsigned)(v >> 32); }

// Rare-path scalar argmin recompute excluding up to 3 consumed indices.
__device__ __forceinline__ unsigned recompute_min(
    const ull* px2, const ull* py2, const ull* c2,
    float bx, float by, unsigned lane,
    unsigned e0, unsigned e1, unsigned e2)
{
    unsigned l = 0xFFFFFFFFu;
    #pragma unroll
    for (int p = 0; p < 4; p++) {
        float pxl = __uint_as_float(lo32(px2[p]));
        float pxh = __uint_as_float(hi32(px2[p]));
        float pyl = __uint_as_float(lo32(py2[p]));
        float pyh = __uint_as_float(hi32(py2[p]));
        float cl  = __uint_as_float(lo32(c2[p]));
        float ch  = __uint_as_float(hi32(c2[p]));
        unsigned g0 = 8u * lane + 2u * (unsigned)p, g1 = g0 + 1u;
        float dl = fmaf(bx, pxl, fmaf(by, pyl, cl));
        float dh = fmaf(bx, pxh, fmaf(by, pyh, ch));
        unsigned k0 = (__float_as_uint(dl) & 0xFFFFFF00u) | g0;
        unsigned k1 = (__float_as_uint(dh) & 0xFFFFFF00u) | g1;
        bool dead0 = (g0 == e0) || (g0 == e1) || (g0 == e2);
        bool dead1 = (g1 == e0) || (g1 == e1) || (g1 == e2);
        l = min(l, dead0 ? 0xFFFFFFFFu : k0);
        l = min(l, dead1 ? 0xFFFFFFFFu : k1);
    }
    return __reduce_min_sync(0xFFFFFFFFu, l);
}

#define NO_EXCL 0x1FFu   // indices are <= 255

// One warp per batch. blockDim = 32, grid = 2048.
// Point k = 8*lane + slot (true input index -> tie-break matches ref).
// FOUR targets per iteration on one snapshot; sequential warp-uniform
// collision checks with rare scalar-recompute fallback keep greedy order.
__global__ __launch_bounds__(32, 1) void match_kernel(const float* __restrict__ inp,
                                                      const float* __restrict__ tgt,
                                                      float* __restrict__ out) {
    const int lane = threadIdx.x;
    const int b = blockIdx.x;

    // Each target j stored as (-2x, -2x, -2y, -2y): one broadcast LDS.128
    // yields both packed f32x2 coefficient registers.
    __shared__ float4 s_tgt4[NPTS];
    // Stride 10 floats (40 B)/lane: 8B-aligned pair loads, conflict-free.
    __shared__ float s_c[10 * 32];

    // Stage targets; sum |t|^2 from raw values.
    const float4* tg4 = (const float4*)(tgt + (size_t)b * 2 * NPTS);
    float tts = 0.0f;
    #pragma unroll
    for (int i = 0; i < 4; i++) {
        float4 v = tg4[lane + 32 * i];      // targets 2*(lane+32i), +1
        tts += fmaf(v.x, v.x, v.y * v.y) + fmaf(v.z, v.z, v.w * v.w);
        int t0 = 2 * (lane + 32 * i);
        s_tgt4[t0]     = make_float4(-2.0f * v.x, -2.0f * v.x,
                                     -2.0f * v.y, -2.0f * v.y);
        s_tgt4[t0 + 1] = make_float4(-2.0f * v.z, -2.0f * v.z,
                                     -2.0f * v.w, -2.0f * v.w);
    }

    // Own 8 consecutive points (coalesced float4): k = 8*lane + i,
    // kept as packed f32x2 pairs (points 2p, 2p+1).
    ull px2[4], py2[4];
    const float4* in4 = (const float4*)(inp + (size_t)b * 2 * NPTS);
    #pragma unroll
    for (int p = 0; p < 4; p++) {
        float4 v = in4[4 * lane + p];       // (x2p, y2p, x2p+1, y2p+1)
        px2[p] = pk2(v.x, v.z);
        py2[p] = pk2(v.y, v.w);
        // c = |p|^2 + 64 (keeps d positive so uint-min == float-min);
        // becomes 1e30 once used.
        s_c[10 * lane + 2 * p]     = fmaf(v.x, v.x, fmaf(v.y, v.y, 64.0f));
        s_c[10 * lane + 2 * p + 1] = fmaf(v.z, v.z, fmaf(v.w, v.w, 64.0f));
    }

    __syncwarp();

    float acc = 0.0f;   // uniform across lanes

    #pragma unroll 1
    for (int jj = 0; jj < NPTS / 4; jj++) {
        float4 tA = s_tgt4[4 * jj + 0];
        float4 tB = s_tgt4[4 * jj + 1];
        float4 tC = s_tgt4[4 * jj + 2];
        float4 tD = s_tgt4[4 * jj + 3];
        ull aX = pk2(tA.x, tA.y), aY = pk2(tA.z, tA.w);
        ull bX = pk2(tB.x, tB.y), bY = pk2(tB.z, tB.w);
        ull cX = pk2(tC.x, tC.y), cY = pk2(tC.z, tC.w);
        ull dX = pk2(tD.x, tD.y), dY = pk2(tD.z, tD.w);

        // Snapshot of c, shared by all 4 targets (and the fallback path).
        ull c2[4];
        #pragma unroll
        for (int p = 0; p < 4; p++)
            c2[p] = *(const ull*)&s_c[10 * lane + 2 * p];

        // d = |t-p|^2 - |t|^2 + 64 > 0, two points per FFMA2 chain.
        // Two running-min accumulators per target (shorter dep chains).
        unsigned mA0 = ~0u, mA1 = ~0u, mB0 = ~0u, mB1 = ~0u;
        unsigned mC0 = ~0u, mC1 = ~0u, mD0 = ~0u, mD1 = ~0u;
        #pragma unroll
        for (int p = 0; p < 4; p++) {
            unsigned g0 = 8u * (unsigned)lane + 2u * (unsigned)p;
            unsigned g1 = g0 + 1u;
            ull base = ffma2(aY, py2[p], c2[p]);          // reuse nothing; 4 chains
            ull eA = ffma2(aX, px2[p], base);
            ull eB = ffma2(bX, px2[p], ffma2(bY, py2[p], c2[p]));
            ull eC = ffma2(cX, px2[p], ffma2(cY, py2[p], c2[p]));
            ull eD = ffma2(dX, px2[p], ffma2(dY, py2[p], c2[p]));
            mA0 = min(mA0, (lo32(eA) & 0xFFFFFF00u) | g0);
            mA1 = min(mA1, (hi32(eA) & 0xFFFFFF00u) | g1);
            mB0 = min(mB0, (lo32(eB) & 0xFFFFFF00u) | g0);
            mB1 = min(mB1, (hi32(eB) & 0xFFFFFF00u) | g1);
            mC0 = min(mC0, (lo32(eC) & 0xFFFFFF00u) | g0);
            mC1 = min(mC1, (hi32(eC) & 0xFFFFFF00u) | g1);
            mD0 = min(mD0, (lo32(eD) & 0xFFFFFF00u) | g0);
            mD1 = min(mD1, (hi32(eD) & 0xFFFFFF00u) | g1);
        }
        // Four REDUXes back-to-back: latencies overlap.
        unsigned kw0 = __reduce_min_sync(~0u, min(mA0, mA1));
        unsigned kw1 = __reduce_min_sync(~0u, min(mB0, mB1));
        unsigned kw2 = __reduce_min_sync(~0u, min(mC0, mC1));
        unsigned kw3 = __reduce_min_sync(~0u, min(mD0, mD1));

        // Sequential greedy resolution (warp-uniform branches, rarely taken).
        // Removing a non-winning element never changes a min, so kw_t is
        // valid unless its index collides with an earlier winner.
        unsigned i0 = kw0 & 0xFFu;
        if (((kw1 ^ kw0) & 0xFFu) == 0u)
            kw1 = recompute_min(px2, py2, c2, tB.x, tB.z, (unsigned)lane,
                                i0, NO_EXCL, NO_EXCL);
        unsigned i1 = kw1 & 0xFFu;
        if ((((kw2 ^ kw0) & 0xFFu) == 0u) | (((kw2 ^ kw1) & 0xFFu) == 0u))
            kw2 = recompute_min(px2, py2, c2, tC.x, tC.z, (unsigned)lane,
                                i0, i1, NO_EXCL);
        unsigned i2 = kw2 & 0xFFu;
        if ((((kw3 ^ kw0) & 0xFFu) == 0u) | (((kw3 ^ kw1) & 0xFFu) == 0u) |
            (((kw3 ^ kw2) & 0xFFu) == 0u))
            kw3 = recompute_min(px2, py2, c2, tD.x, tD.z, (unsigned)lane,
                                i0, i1, i2);
        unsigned i3 = kw3 & 0xFFu;

        // Apply all 4 kills, then one syncwarp before next quad's c load.
        if ((i0 >> 3) == (unsigned)lane) s_c[10 * lane + (i0 & 7u)] = 1e30f;
        if ((i1 >> 3) == (unsigned)lane) s_c[10 * lane + (i1 & 7u)] = 1e30f;
        if ((i2 >> 3) == (unsigned)lane) s_c[10 * lane + (i2 & 7u)] = 1e30f;
        if ((i3 >> 3) == (unsigned)lane) s_c[10 * lane + (i3 & 7u)] = 1e30f;

        // Uniform accumulate; index bits are denormal-magnitude noise and
        // 8-bit truncation bias ~2^-16 relative: both << 1e-3 tolerance.
        acc += (__uint_as_float(kw0) + __uint_as_float(kw1)) +
               (__uint_as_float(kw2) + __uint_as_float(kw3));

        __syncwarp();
    }

    // Sum of |t|^2 over the batch (warp butterfly, off critical path).
    #pragma unroll
    for (int off = 16; off; off >>= 1)
        tts += __shfl_xor_sync(0xffffffffu, tts, off);

    // se_j = d_j - 64 + |t_j|^2  =>  batch sum = acc + tts - 64*256
    if (lane == 0) g_partial[b] = acc + tts - 64.0f * NPTS;
    __threadfence();

    // Fused deterministic final reduction (last block, fixed order, fp64).
    int last = 0;
    if (lane == 0) last = (atomicAdd(&g_ctr, 1) == B_TOTAL - 1);
    last = __shfl_sync(0xffffffffu, last, 0);
    if (last) {
        __threadfence();
        double s = 0.0;
        #pragma unroll
        for (int i = 0; i < B_TOTAL / 32; i++)
            s += (double)g_partial[lane + 32 * i];
        #pragma unroll
        for (int off = 16; off; off >>= 1)
            s += __shfl_xor_sync(0xffffffffu, s, off);
        if (lane == 0) {
            out[0] = (float)(s / (double)B_TOTAL / (double)(2 * NPTS));
            g_ctr = 0;                  // reset for next graph replay
        }
    }
}

extern "C" void kernel_launch(void* const* d_in, const int* in_sizes, int n_in,
                              void* d_out, int out_size) {
    const float* inp = (const float*)d_in[0];   // "input"
    const float* tgt = (const float*)d_in[1];   // "targets"
    match_kernel<<<B_TOTAL, 32>>>(inp, tgt, (float*)d_out);
}

// round 14
// speedup vs baseline: 1.0271x; 1.0271x over previous
#include <cuda_runtime.h>

#define B_TOTAL 2048
#define NPTS    256

typedef unsigned long long ull;

__device__ float g_partial[B_TOTAL];
__device__ int   g_ctr;    // zero-init; last block resets it each run

__device__ __forceinline__ ull pk2(float lo, float hi) {
    ull r; asm("mov.b64 %0, {%1, %2};" : "=l"(r) : "f"(lo), "f"(hi)); return r;
}
// Packed 2-wide fp32 FMA (sm_103a FFMA2; only reachable via PTX f32x2).
__device__ __forceinline__ ull ffma2(ull a, ull b, ull c) {
    ull d; asm("fma.rn.f32x2 %0, %1, %2, %3;" : "=l"(d) : "l"(a), "l"(b), "l"(c));
    return d;
}
__device__ __forceinline__ unsigned lo32(ull v) { return (unsigned)v; }
__device__ __forceinline__ unsigned hi32(ull v) { return (unsigned)(v >> 32); }

#define NO_EXCL 0x1FFu   // real indices are <= 255

// Rare-path scalar argmin recompute excluding up to 3 consumed indices.
__device__ __forceinline__ unsigned recompute_min(
    const ull* px2, const ull* py2, const ull* c2,
    float bx, float by, unsigned lane,
    unsigned e0, unsigned e1, unsigned e2)
{
    unsigned l = 0xFFFFFFFFu;
    #pragma unroll
    for (int p = 0; p < 4; p++) {
        float pxl = __uint_as_float(lo32(px2[p]));
        float pxh = __uint_as_float(hi32(px2[p]));
        float pyl = __uint_as_float(lo32(py2[p]));
        float pyh = __uint_as_float(hi32(py2[p]));
        float cl  = __uint_as_float(lo32(c2[p]));
        float ch  = __uint_as_float(hi32(c2[p]));
        unsigned g0 = 8u * lane + 2u * (unsigned)p, g1 = g0 + 1u;
        float dl = fmaf(bx, pxl, fmaf(by, pyl, cl));
        float dh = fmaf(bx, pxh, fmaf(by, pyh, ch));
        unsigned k0 = (__float_as_uint(dl) & 0xFFFFFF00u) | g0;
        unsigned k1 = (__float_as_uint(dh) & 0xFFFFFF00u) | g1;
        bool dead0 = (g0 == e0) || (g0 == e1) || (g0 == e2);
        bool dead1 = (g1 == e0) || (g1 == e1) || (g1 == e2);
        l = min(l, dead0 ? 0xFFFFFFFFu : k0);
        l = min(l, dead1 ? 0xFFFFFFFFu : k1);
    }
    return __reduce_min_sync(0xFFFFFFFFu, l);
}

// One warp per batch. blockDim = 32, grid = 2048.
// Point k = 8*lane + slot (true input index -> tie-break matches ref).
// FOUR targets per iteration on one snapshot. All collision checks are
// computed in parallel from the 4 original winners -> ONE rare warp-uniform
// fallback branch per quad (sequential recompute inside).
__global__ __launch_bounds__(32, 1) void match_kernel(const float* __restrict__ inp,
                                                      const float* __restrict__ tgt,
                                                      float* __restrict__ out) {
    const int lane = threadIdx.x;
    const int b = blockIdx.x;

    // Each target j stored as (-2x, -2x, -2y, -2y): one broadcast LDS.128
    // yields both packed f32x2 coefficient registers.
    __shared__ float4 s_tgt4[NPTS];
    // Stride 12 floats (48 B)/lane: 16B-aligned -> c snapshot in 2 LDS.128;
    // bank pattern 12*lane mod 32 distinct within each 8-lane phase.
    __shared__ __align__(16) float s_c[12 * 32];

    // Stage targets; sum |t|^2 from raw values.
    const float4* tg4 = (const float4*)(tgt + (size_t)b * 2 * NPTS);
    float tts = 0.0f;
    #pragma unroll
    for (int i = 0; i < 4; i++) {
        float4 v = tg4[lane + 32 * i];      // targets 2*(lane+32i), +1
        tts += fmaf(v.x, v.x, v.y * v.y) + fmaf(v.z, v.z, v.w * v.w);
        int t0 = 2 * (lane + 32 * i);
        s_tgt4[t0]     = make_float4(-2.0f * v.x, -2.0f * v.x,
                                     -2.0f * v.y, -2.0f * v.y);
        s_tgt4[t0 + 1] = make_float4(-2.0f * v.z, -2.0f * v.z,
                                     -2.0f * v.w, -2.0f * v.w);
    }

    // Own 8 consecutive points (coalesced float4): k = 8*lane + i,
    // kept as packed f32x2 pairs (points 2p, 2p+1).
    ull px2[4], py2[4];
    const float4* in4 = (const float4*)(inp + (size_t)b * 2 * NPTS);
    #pragma unroll
    for (int p = 0; p < 4; p++) {
        float4 v = in4[4 * lane + p];       // (x2p, y2p, x2p+1, y2p+1)
        px2[p] = pk2(v.x, v.z);
        py2[p] = pk2(v.y, v.w);
        // c = |p|^2 + 64 (keeps d positive so uint-min == float-min);
        // becomes 1e30 once used.
        s_c[12 * lane + 2 * p]     = fmaf(v.x, v.x, fmaf(v.y, v.y, 64.0f));
        s_c[12 * lane + 2 * p + 1] = fmaf(v.z, v.z, fmaf(v.w, v.w, 64.0f));
    }

    __syncwarp();

    float acc = 0.0f;   // uniform across lanes

    #pragma unroll 1
    for (int jj = 0; jj < NPTS / 4; jj++) {
        float4 tA = s_tgt4[4 * jj + 0];
        float4 tB = s_tgt4[4 * jj + 1];
        float4 tC = s_tgt4[4 * jj + 2];
        float4 tD = s_tgt4[4 * jj + 3];
        ull aX = pk2(tA.x, tA.y), aY = pk2(tA.z, tA.w);
        ull bX = pk2(tB.x, tB.y), bY = pk2(tB.z, tB.w);
        ull cX = pk2(tC.x, tC.y), cY = pk2(tC.z, tC.w);
        ull dX = pk2(tD.x, tD.y), dY = pk2(tD.z, tD.w);

        // Snapshot of c in two LDS.128; shared by 4 targets + fallback.
        ulonglong2 cc0 = *(const ulonglong2*)&s_c[12 * lane];
        ulonglong2 cc1 = *(const ulonglong2*)&s_c[12 * lane + 4];
        ull c2[4] = { cc0.x, cc0.y, cc1.x, cc1.y };

        // d = |t-p|^2 - |t|^2 + 64 > 0, two points per FFMA2 chain.
        // Two running-min accumulators per target (4-deep chains).
        unsigned mA0 = ~0u, mA1 = ~0u, mB0 = ~0u, mB1 = ~0u;
        unsigned mC0 = ~0u, mC1 = ~0u, mD0 = ~0u, mD1 = ~0u;
        #pragma unroll
        for (int p = 0; p < 4; p++) {
            unsigned g0 = 8u * (unsigned)lane + 2u * (unsigned)p;
            unsigned g1 = g0 + 1u;
            ull eA = ffma2(aX, px2[p], ffma2(aY, py2[p], c2[p]));
            ull eB = ffma2(bX, px2[p], ffma2(bY, py2[p], c2[p]));
            ull eC = ffma2(cX, px2[p], ffma2(cY, py2[p], c2[p]));
            ull eD = ffma2(dX, px2[p], ffma2(dY, py2[p], c2[p]));
            mA0 = min(mA0, (lo32(eA) & 0xFFFFFF00u) | g0);
            mA1 = min(mA1, (hi32(eA) & 0xFFFFFF00u) | g1);
            mB0 = min(mB0, (lo32(eB) & 0xFFFFFF00u) | g0);
            mB1 = min(mB1, (hi32(eB) & 0xFFFFFF00u) | g1);
            mC0 = min(mC0, (lo32(eC) & 0xFFFFFF00u) | g0);
            mC1 = min(mC1, (hi32(eC) & 0xFFFFFF00u) | g1);
            mD0 = min(mD0, (lo32(eD) & 0xFFFFFF00u) | g0);
            mD1 = min(mD1, (hi32(eD) & 0xFFFFFF00u) | g1);
        }
        // Four independent REDUXes back-to-back: latencies overlap.
        unsigned kw0 = __reduce_min_sync(~0u, min(mA0, mA1));
        unsigned kw1 = __reduce_min_sync(~0u, min(mB0, mB1));
        unsigned kw2 = __reduce_min_sync(~0u, min(mC0, mC1));
        unsigned kw3 = __reduce_min_sync(~0u, min(mD0, mD1));

        unsigned i0 = kw0 & 0xFFu, i1 = kw1 & 0xFFu;
        unsigned i2 = kw2 & 0xFFu, i3 = kw3 & 0xFFu;

        // Parallel collision detection on the ORIGINAL winners; one branch.
        bool col = (i1 == i0) |
                   (i2 == i0) | (i2 == i1) |
                   (i3 == i0) | (i3 == i1) | (i3 == i2);
        if (col) {
            // Sequential greedy repair (rare, ~11% of quads). Recomputing a
            // non-colliding target with earlier winners excluded is a no-op
            // (removing non-winning elements never changes a min).
            kw1 = recompute_min(px2, py2, c2, tB.x, tB.z, (unsigned)lane,
                                i0, NO_EXCL, NO_EXCL);
            i1 = kw1 & 0xFFu;
            kw2 = recompute_min(px2, py2, c2, tC.x, tC.z, (unsigned)lane,
                                i0, i1, NO_EXCL);
            i2 = kw2 & 0xFFu;
            kw3 = recompute_min(px2, py2, c2, tD.x, tD.z, (unsigned)lane,
                                i0, i1, i2);
            i3 = kw3 & 0xFFu;
        }

        // Apply all 4 kills (predicated STS), then one syncwarp.
        if ((i0 >> 3) == (unsigned)lane) s_c[12 * lane + (i0 & 7u)] = 1e30f;
        if ((i1 >> 3) == (unsigned)lane) s_c[12 * lane + (i1 & 7u)] = 1e30f;
        if ((i2 >> 3) == (unsigned)lane) s_c[12 * lane + (i2 & 7u)] = 1e30f;
        if ((i3 >> 3) == (unsigned)lane) s_c[12 * lane + (i3 & 7u)] = 1e30f;

        // Uniform accumulate; index bits are denormal-magnitude noise and
        // 8-bit truncation bias ~2^-16 relative: both << 1e-3 tolerance.
        acc += (__uint_as_float(kw0) + __uint_as_float(kw1)) +
               (__uint_as_float(kw2) + __uint_as_float(kw3));

        __syncwarp();
    }

    // Sum of |t|^2 over the batch (warp butterfly, off critical path).
    #pragma unroll
    for (int off = 16; off; off >>= 1)
        tts += __shfl_xor_sync(0xffffffffu, tts, off);

    // se_j = d_j - 64 + |t_j|^2  =>  batch sum = acc + tts - 64*256
    if (lane == 0) g_partial[b] = acc + tts - 64.0f * NPTS;
    __threadfence();

    // Fused deterministic final reduction (last block, fixed order, fp64).
    int last = 0;
    if (lane == 0) last = (atomicAdd(&g_ctr, 1) == B_TOTAL - 1);
    last = __shfl_sync(0xffffffffu, last, 0);
    if (last) {
        __threadfence();
        double s = 0.0;
        #pragma unroll
        for (int i = 0; i < B_TOTAL / 32; i++)
            s += (double)g_partial[lane + 32 * i];
        #pragma unroll
        for (int off = 16; off; off >>= 1)
            s += __shfl_xor_sync(0xffffffffu, s, off);
        if (lane == 0) {
            out[0] = (float)(s / (double)B_TOTAL / (double)(2 * NPTS));
            g_ctr = 0;                  // reset for next graph replay
        }
    }
}

extern "C" void kernel_launch(void* const* d_in, const int* in_sizes, int n_in,
                              void* d_out, int out_size) {
    const float* inp = (const float*)d_in[0];   // "input"
    const float* tgt = (const float*)d_in[1];   // "targets"
    match_kernel<<<B_TOTAL, 32>>>(inp, tgt, (float*)d_out);
}